// round 2
// baseline (speedup 1.0000x reference)
#include <cuda_runtime.h>
#include <cstdint>

// ----------------------------------------------------------------------------
// VectorQuantizerEMA: z [64,4096,64] f32, embedding [512,64] f32
// Outputs (concatenated f32, tuple order):
//   z_q_st [16777216], loss [1], indices [262144], new_embedding [32768],
//   new_cluster_size [512], new_embedding_avg [32768]   -> total 17105409
// ----------------------------------------------------------------------------

#define NC      512
#define CD      64
#define NROWS   (64 * 4096)              // 262144
#define NELEM   (NROWS * CD)             // 16777216

// output offsets
#define O_ZQ    ((size_t)0)
#define O_LOSS  ((size_t)16777216)
#define O_IDX   ((size_t)16777217)
#define O_NEMB  ((size_t)17039361)
#define O_NCS   ((size_t)17072129)
#define O_NAVG  ((size_t)17072641)

typedef unsigned long long ull;

// scratch (device globals: no allocation in kernel_launch)
__device__ __align__(16) float g_esum[NC * CD];
__device__ float g_counts[NC];
__device__ float g_h[NC];      // 0.5 * ||e_j||^2
__device__ float g_sse;

// ---- packed f32x2 helpers (Blackwell) --------------------------------------
__device__ __forceinline__ void fma2(ull& acc, ull a, ull b) {
    asm("fma.rn.f32x2 %0, %1, %2, %0;" : "+l"(acc) : "l"(a), "l"(b));
}
__device__ __forceinline__ ull add2(ull a, ull b) {
    ull d; asm("add.rn.f32x2 %0, %1, %2;" : "=l"(d) : "l"(a), "l"(b)); return d;
}
__device__ __forceinline__ float2 unpack2(ull v) {
    float2 r; asm("mov.b64 {%0, %1}, %2;" : "=f"(r.x), "=f"(r.y) : "l"(v)); return r;
}

// ----------------------------------------------------------------------------
// Kernel 1: zero scratch, precompute half-norms
// ----------------------------------------------------------------------------
__global__ void vq_init(const float* __restrict__ emb) {
    int t = blockIdx.x * blockDim.x + threadIdx.x;
    if (t < NC * CD) g_esum[t] = 0.0f;
    if (t == 0) g_sse = 0.0f;
    if (blockIdx.x == 0 && t < NC) {
        g_counts[t] = 0.0f;
        const float4* e = (const float4*)(emb + (size_t)t * CD);
        float s = 0.0f;
#pragma unroll
        for (int i = 0; i < CD / 4; i++) {
            float4 v = e[i];
            s += v.x * v.x + v.y * v.y + v.z * v.z + v.w * v.w;
        }
        g_h[t] = 0.5f * s;
    }
}

// ----------------------------------------------------------------------------
// Kernel 2: main — one thread per row. Codebook in smem (128KB), broadcast
// LDS.128 + packed fma.rn.f32x2 inner loop, argmax of (f.e - 0.5||e||^2).
// ----------------------------------------------------------------------------
__global__ void __launch_bounds__(512, 1)
vq_main(const float* __restrict__ z, float* __restrict__ out) {
    extern __shared__ __align__(16) ull smemraw[];
    ull*   sE   = smemraw;                         // 512 codes * 32 ull = 128KB
    float* sH   = (float*)(sE + NC * (CD / 2));    // 512 f
    float* sCnt = sH + NC;                         // 512 f

    // stage codebook + half-norms, zero smem histogram
    {
        // reuse: codebook already resident in L2; read via g_esum? No — read
        // from the global embedding copy the init kernel consumed. We re-read
        // from out? Cleanest: codebook passed implicitly via g_h + raw E.
    }
    // NOTE: E is staged from the const input pointer passed through g? We pass
    // emb via kernel arg instead:
    // (see vq_main2 wrapper below)
    (void)z; (void)out; (void)sCnt;
}

// real main kernel (takes emb pointer too)
__global__ void __launch_bounds__(512, 1)
vq_main2(const float* __restrict__ z, const float* __restrict__ emb,
         float* __restrict__ out) {
    extern __shared__ __align__(16) ull smemraw[];
    ull*   sE   = smemraw;                         // 128 KB
    float* sH   = (float*)(sE + NC * (CD / 2));
    float* sCnt = sH + NC;

    const ull* gE = (const ull*)emb;
    for (int i = threadIdx.x; i < NC * (CD / 2); i += 512) sE[i] = gE[i];
    for (int i = threadIdx.x; i < NC; i += 512) { sH[i] = g_h[i]; sCnt[i] = 0.0f; }
    __syncthreads();

    const int r = blockIdx.x * 512 + threadIdx.x;  // grid chosen so r < NROWS

    // load row into registers (packed pairs)
    ull f2[CD / 2];
    {
        const ulonglong2* fp = (const ulonglong2*)(z + (size_t)r * CD);
#pragma unroll
        for (int i = 0; i < CD / 4; i++) {
            ulonglong2 v = fp[i];
            f2[2 * i] = v.x; f2[2 * i + 1] = v.y;
        }
    }

    float best = -3.4e38f;
    int   bi   = 0;
#pragma unroll 1
    for (int j = 0; j < NC; j++) {
        const ulonglong2* e = (const ulonglong2*)(sE + j * (CD / 2));
        ull a0 = 0, a1 = 0, a2 = 0, a3 = 0;   // 0x0 == packed {+0.f,+0.f}
#pragma unroll
        for (int c = 0; c < CD / 8; c++) {    // 8 iters, 4 chains
            ulonglong2 v0 = e[2 * c];
            ulonglong2 v1 = e[2 * c + 1];
            fma2(a0, f2[4 * c + 0], v0.x);
            fma2(a1, f2[4 * c + 1], v0.y);
            fma2(a2, f2[4 * c + 2], v1.x);
            fma2(a3, f2[4 * c + 3], v1.y);
        }
        float2 p = unpack2(add2(add2(a0, a1), add2(a2, a3)));
        float s = (p.x + p.y) - sH[j];
        if (s > best) { best = s; bi = j; }    // strict '>' keeps lowest index
    }

    // ---- per-row epilogue ----
    out[O_IDX + r] = (float)bi;
    atomicAdd(&sCnt[bi], 1.0f);

    float*  orow = out + O_ZQ + (size_t)r * CD;
    float4* esum = (float4*)(g_esum + bi * CD);
    const ulonglong2* e = (const ulonglong2*)(sE + bi * (CD / 2));
    float lsse = 0.0f;
#pragma unroll
    for (int c = 0; c < CD / 4; c++) {
        ulonglong2 v = e[c];
        float2 e0 = unpack2(v.x), e1 = unpack2(v.y);
        float2 z0 = unpack2(f2[2 * c]), z1 = unpack2(f2[2 * c + 1]);
        float d0 = e0.x - z0.x, d1 = e0.y - z0.y;
        float d2 = e1.x - z1.x, d3 = e1.y - z1.y;
        lsse += d0 * d0 + d1 * d1 + d2 * d2 + d3 * d3;
        float4 q = make_float4(z0.x + d0, z0.y + d1, z1.x + d2, z1.y + d3);
        ((float4*)orow)[c] = q;
        // embed_sum accumulates FLAT (z), not e
        atomicAdd(&esum[c], make_float4(z0.x, z0.y, z1.x, z1.y));
    }

    // SSE: warp reduce, one global RED per warp
#pragma unroll
    for (int o = 16; o; o >>= 1) lsse += __shfl_xor_sync(0xffffffffu, lsse, o);
    if ((threadIdx.x & 31) == 0) atomicAdd(&g_sse, lsse);

    __syncthreads();
    for (int i = threadIdx.x; i < NC; i += 512) {
        float c = sCnt[i];
        if (c != 0.0f) atomicAdd(&g_counts[i], c);
    }
}

// ----------------------------------------------------------------------------
// Kernel 3: finalize EMA + loss. One block, 512 threads (one per code).
// ----------------------------------------------------------------------------
__global__ void vq_final(const float* __restrict__ cluster_size,
                         const float* __restrict__ embedding_avg,
                         float* __restrict__ out) {
    __shared__ float red[NC];
    const int j = threadIdx.x;

    float cnt = g_counts[j];
    float ncs = cluster_size[j] * 0.99f + 0.01f * cnt;
    out[O_NCS + j] = ncs;

    red[j] = ncs;
    __syncthreads();
#pragma unroll
    for (int o = NC / 2; o > 0; o >>= 1) {
        if (j < o) red[j] += red[j + o];
        __syncthreads();
    }
    float n  = red[0];
    float cs = (ncs + 1e-6f) / (n + (float)NC * 1e-6f);

#pragma unroll 4
    for (int k = 0; k < CD; k++) {
        float ea = embedding_avg[(size_t)j * CD + k] * 0.99f
                 + 0.01f * g_esum[(size_t)j * CD + k];
        out[O_NAVG + (size_t)j * CD + k] = ea;
        out[O_NEMB + (size_t)j * CD + k] = ea / cs;
    }

    if (j == 0) out[O_LOSS] = 0.25f * g_sse / (float)NELEM;
}

// ----------------------------------------------------------------------------
extern "C" void kernel_launch(void* const* d_in, const int* in_sizes, int n_in,
                              void* d_out, int out_size) {
    const float* z    = (const float*)d_in[0];  // [64,4096,64]
    const float* emb  = (const float*)d_in[1];  // [512,64]
    const float* csz  = (const float*)d_in[2];  // [512]
    const float* eavg = (const float*)d_in[3];  // [512,64]
    float* out = (float*)d_out;

    const int smem = NC * CD * 4 + NC * 4 + NC * 4;   // 135168 B
    cudaFuncSetAttribute(vq_main2, cudaFuncAttributeMaxDynamicSharedMemorySize, smem);

    vq_init<<<64, 512>>>(emb);
    vq_main2<<<NROWS / 512, 512, smem>>>(z, emb, out);
    vq_final<<<1, NC>>>(csz, eavg, out);
}

// round 5
// speedup vs baseline: 1.6330x; 1.6330x over previous
#include <cuda_runtime.h>
#include <cuda_fp16.h>
#include <cstdint>

// ============================================================================
// VectorQuantizerEMA via mma.sync m16n8k16 (HMMA, sm_80-level PTX).
// fp16-split exact-margin scheme: s = f.e - 0.5||e||^2 via (f_hi+f_lo).e_hi,
// low-margin rows re-checked in exact fp32.
// ============================================================================

#define NC      512
#define CD      64
#define NROWS   (64 * 4096)
#define NELEM   (NROWS * CD)
#define TAU     0.12f

#define O_ZQ    ((size_t)0)
#define O_LOSS  ((size_t)16777216)
#define O_IDX   ((size_t)16777217)
#define O_NEMB  ((size_t)17039361)
#define O_NCS   ((size_t)17072129)
#define O_NAVG  ((size_t)17072641)

// ---- device scratch --------------------------------------------------------
__device__ __align__(16) float g_esum[NC * CD];
__device__ __align__(16) unsigned short g_Bh[NC * CD];  // fp16 E, swizzled
__device__ float g_counts[NC];
__device__ float g_h[NC];            // 0.5*||e||^2
__device__ float g_sse;

// ---- smem layout (bytes) ---------------------------------------------------
#define SM_B     0        // 64KB: fp16 B staging / fp32 E halves (recheck)
#define SM_AH    65536    // 16KB: A hi fp16, swizzled
#define SM_AL    81920    // 16KB: A lo fp16, swizzled
#define SM_RED   98304    // 32KB: 128 rows x 16 warps x float4
#define SM_H     131072   // 2KB
#define SM_CNT   133120   // 2KB
#define SM_BI    135168   // 512B
#define SM_LIST  135680   // 512B
#define SM_NFLG  136192   // 4B
#define SMEM_SZ  136448

__device__ __forceinline__ uint32_t smem_u32(const void* p) {
    uint32_t a;
    asm("{ .reg .u64 t; cvta.to.shared.u64 t, %1; cvt.u32.u64 %0, t; }" : "=r"(a) : "l"(p));
    return a;
}
__device__ __forceinline__ void ldsm_x4(uint32_t a, uint32_t* r) {
    asm volatile("ldmatrix.sync.aligned.m8n8.x4.shared.b16 {%0,%1,%2,%3}, [%4];"
        : "=r"(r[0]), "=r"(r[1]), "=r"(r[2]), "=r"(r[3]) : "r"(a));
}
__device__ __forceinline__ void mma16816(float* c, const uint32_t* a, const uint32_t* b) {
    asm volatile("mma.sync.aligned.m16n8k16.row.col.f32.f16.f16.f32 "
        "{%0,%1,%2,%3}, {%4,%5,%6,%7}, {%8,%9}, {%0,%1,%2,%3};"
        : "+f"(c[0]), "+f"(c[1]), "+f"(c[2]), "+f"(c[3])
        : "r"(a[0]), "r"(a[1]), "r"(a[2]), "r"(a[3]), "r"(b[0]), "r"(b[1]));
}
__device__ __forceinline__ void splitpack(float x, float y, uint32_t& hi, uint32_t& lo) {
    __half hx = __float2half_rn(x), hy = __float2half_rn(y);
    float rx = __half2float(hx), ry = __half2float(hy);
    __half lx = __float2half_rn(x - rx), ly = __float2half_rn(y - ry);
    hi = ((uint32_t)__half_as_ushort(hy) << 16) | __half_as_ushort(hx);
    lo = ((uint32_t)__half_as_ushort(ly) << 16) | __half_as_ushort(lx);
}

// ============================================================================
// Kernel 1: zero scratch, half-norms, fp16-swizzled B
// ============================================================================
__global__ void vq_init(const float* __restrict__ emb) {
    int t = blockIdx.x * blockDim.x + threadIdx.x;   // 64 x 512 = 32768
    if (t < NC * CD) {
        g_esum[t] = 0.0f;
        int j = t >> 6, k = t & 63;
        // 16B-chunk swizzle within a 128B row: chunk' = chunk ^ (code & 7)
        g_Bh[(j << 6) + ((((k >> 3) ^ (j & 7)) & 7) << 3) + (k & 7)] =
            __half_as_ushort(__float2half_rn(emb[t]));
    }
    if (t == 0) g_sse = 0.0f;
    if (t < NC) {
        g_counts[t] = 0.0f;
        const float4* e = (const float4*)(emb + (size_t)t * CD);
        float s = 0.0f;
#pragma unroll
        for (int i = 0; i < CD / 4; i++) {
            float4 v = e[i];
            s += v.x * v.x + v.y * v.y + v.z * v.z + v.w * v.w;
        }
        g_h[t] = 0.5f * s;
    }
}

// ============================================================================
// Kernel 2: main. 2048 CTAs x 512 thr (16 warps). 128 rows/CTA.
// Warp w owns codes [32w, 32w+32) (B fragments register-resident).
// ============================================================================
__global__ void __launch_bounds__(512, 1)
vq_main(const float* __restrict__ z, const float* __restrict__ emb,
        float* __restrict__ out) {
    extern __shared__ __align__(16) char smem[];
    const uint32_t sb32 = smem_u32(smem);
    float* sH   = (float*)(smem + SM_H);
    float* sCnt = (float*)(smem + SM_CNT);
    int*   sBI  = (int*)(smem + SM_BI);
    int*   sLst = (int*)(smem + SM_LIST);
    int*   sNF  = (int*)(smem + SM_NFLG);
    float4* sR  = (float4*)(smem + SM_RED);

    const int tid  = threadIdx.x;
    const int wid  = tid >> 5;
    const int lane = tid & 31;
    const int tile = blockIdx.x;

    // ---- stage B (fp16, pre-swizzled), h, counters ----
    {
        const uint4* gB = (const uint4*)g_Bh;
        uint4* sB = (uint4*)(smem + SM_B);
#pragma unroll
        for (int i = 0; i < 8; i++) sB[tid + 512 * i] = gB[tid + 512 * i];
    }
    sH[tid] = g_h[tid];
    sCnt[tid] = 0.0f;
    if (tid == 0) *sNF = 0;

    // ---- stage A tile hi/lo fp16, swizzled; thread t: row t/4, quarter t%4
    {
        int row = tid >> 2, q = tid & 3;
        const float4* zr = (const float4*)(z + ((size_t)tile * 128 + row) * CD + q * 16);
        float4 v0 = zr[0], v1 = zr[1], v2 = zr[2], v3 = zr[3];
        uint4 H0, L0, H1, L1;
        splitpack(v0.x, v0.y, H0.x, L0.x); splitpack(v0.z, v0.w, H0.y, L0.y);
        splitpack(v1.x, v1.y, H0.z, L0.z); splitpack(v1.z, v1.w, H0.w, L0.w);
        splitpack(v2.x, v2.y, H1.x, L1.x); splitpack(v2.z, v2.w, H1.y, L1.y);
        splitpack(v3.x, v3.y, H1.z, L1.z); splitpack(v3.z, v3.w, H1.w, L1.w);
        uint4* pH = (uint4*)(smem + SM_AH + row * 128);
        uint4* pL = (uint4*)(smem + SM_AL + row * 128);
        int c0 = (2 * q) ^ (row & 7), c1 = (2 * q + 1) ^ (row & 7);
        pH[c0] = H0; pH[c1] = H1;
        pL[c0] = L0; pL[c1] = L1;
    }
    __syncthreads();

    const int jw = wid * 32;
    float hreg[8];
#pragma unroll
    for (int nt = 0; nt < 4; nt++) {
        hreg[nt * 2]     = sH[jw + nt * 8 + 2 * (lane & 3)];
        hreg[nt * 2 + 1] = sH[jw + nt * 8 + 2 * (lane & 3) + 1];
    }

    // ---- hoist B fragments: 2 pairs x 4 ksteps x ldmatrix.x4 (NON-trans) ----
    // lanes 0-7: codes base+0..7 lo-chunk | 8-15: same codes hi-chunk |
    // 16-23: codes base+8..15 lo | 24-31: hi  =>  r0,r1 = {b0,b1} nt=2p ;
    // r2,r3 = {b0,b1} nt=2p+1
    uint32_t Breg[2][4][4];
    {
        int chb = (lane >> 3) & 1;
#pragma unroll
        for (int p = 0; p < 2; p++) {
            int code = jw + p * 16 + (((lane >> 4) & 1) << 3) + (lane & 7);
            uint32_t base = sb32 + SM_B + code * 128;
            int sw = code & 7;
#pragma unroll
            for (int ks = 0; ks < 4; ks++)
                ldsm_x4(base + (((2 * ks + chb) ^ sw) << 4), Breg[p][ks]);
        }
    }

    // ---- mainloop: 8 row-tiles of m16 ----
#pragma unroll 1
    for (int rt = 0; rt < 8; rt++) {
        uint32_t Ah[16], Al[16];
        {
            int rl = 16 * rt + (lane & 7) + (((lane >> 3) & 1) << 3);
            int ch = (lane >> 4) & 1;
            uint32_t baseH = sb32 + SM_AH + rl * 128;
            int sw = rl & 7;
#pragma unroll
            for (int ks = 0; ks < 4; ks++) {
                uint32_t off = ((2 * ks + ch) ^ sw) << 4;
                ldsm_x4(baseH + off, &Ah[ks * 4]);
                ldsm_x4(baseH + off + (SM_AL - SM_AH), &Al[ks * 4]);
            }
        }
        float C[16];
#pragma unroll
        for (int i = 0; i < 16; i++) C[i] = 0.0f;

#pragma unroll
        for (int p = 0; p < 2; p++)
#pragma unroll
            for (int sub = 0; sub < 2; sub++) {
                int nt = 2 * p + sub;
#pragma unroll
                for (int ks = 0; ks < 4; ks++) {
                    mma16816(&C[nt * 4], &Ah[ks * 4], &Breg[p][ks][2 * sub]);
                    mma16816(&C[nt * 4], &Al[ks * 4], &Breg[p][ks][2 * sub]);
                }
            }

        // ---- extraction: rows g=lane/4 and g+8 of this row-tile ----
        float b1a = -3.4e38f, b2a = -3.4e38f; int i1a = 0;
        float b1b = -3.4e38f, b2b = -3.4e38f; int i1b = 0;
#pragma unroll
        for (int nt = 0; nt < 4; nt++) {
#pragma unroll
            for (int u = 0; u < 2; u++) {
                int j = jw + nt * 8 + 2 * (lane & 3) + u;
                float s = C[nt * 4 + u] - hreg[nt * 2 + u];
                if (s > b1a) { b2a = b1a; b1a = s; i1a = j; }
                else if (s > b2a) b2a = s;
                float s2 = C[nt * 4 + 2 + u] - hreg[nt * 2 + u];
                if (s2 > b1b) { b2b = b1b; b1b = s2; i1b = j; }
                else if (s2 > b2b) b2b = s2;
            }
        }
#pragma unroll
        for (int m = 1; m <= 2; m <<= 1) {
            float ob  = __shfl_xor_sync(0xffffffffu, b1a, m);
            float ob2 = __shfl_xor_sync(0xffffffffu, b2a, m);
            int   oi  = __shfl_xor_sync(0xffffffffu, i1a, m);
            bool take = (ob > b1a) || (ob == b1a && oi < i1a);
            float loser = take ? b1a : ob;
            b2a = fmaxf(fmaxf(b2a, ob2), loser);
            if (take) { b1a = ob; i1a = oi; }
            ob  = __shfl_xor_sync(0xffffffffu, b1b, m);
            ob2 = __shfl_xor_sync(0xffffffffu, b2b, m);
            oi  = __shfl_xor_sync(0xffffffffu, i1b, m);
            take = (ob > b1b) || (ob == b1b && oi < i1b);
            loser = take ? b1b : ob;
            b2b = fmaxf(fmaxf(b2b, ob2), loser);
            if (take) { b1b = ob; i1b = oi; }
        }
        if ((lane & 3) == 0) {
            int g = lane >> 2;
            sR[(16 * rt + g) * 16 + wid]     = make_float4(b1a, b2a, __int_as_float(i1a), 0.f);
            sR[(16 * rt + g + 8) * 16 + wid] = make_float4(b1b, b2b, __int_as_float(i1b), 0.f);
        }
    }
    __syncthreads();

    // ---- per-row combine across 16 warps; flag low-margin rows ----
    if (tid < 128) {
        float b = -3.4e38f, b2 = -3.4e38f; int bi = 0;
#pragma unroll
        for (int w = 0; w < 16; w++) {
            float4 v = sR[tid * 16 + w];
            int oi = __float_as_int(v.z);
            bool take = (v.x > b) || (v.x == b && oi < bi);
            float loser = take ? b : v.x;
            b2 = fmaxf(fmaxf(b2, v.y), loser);
            if (take) { b = v.x; bi = oi; }
        }
        sBI[tid] = bi;
        if (b - b2 < TAU) {
            int p = atomicAdd(sNF, 1);
            sLst[p] = tid;
        }
    }
    __syncthreads();
    const int nflag = *sNF;

    // ---- exact fp32 recheck for flagged rows (E staged in 2 halves) ----
    if (nflag > 0) {
#pragma unroll 1
        for (int half = 0; half < 2; half++) {
            {   // stage 256 codes fp32, 16B-chunk swizzled: chunk' = chunk^(c&15)
                int c = tid >> 1;
                int cb = (tid & 1) * 8;
                const float4* src = (const float4*)(emb + (size_t)(half * 256 + c) * CD);
                float4* dst = (float4*)(smem + SM_B + c * 256);
#pragma unroll
                for (int i = 0; i < 8; i++) {
                    int chunk = cb + i;
                    dst[chunk ^ (c & 15)] = src[chunk];
                }
            }
            __syncthreads();
#pragma unroll 1
            for (int li = wid; li < nflag; li += 16) {
                int rowl = sLst[li];
                const float4* zr = (const float4*)(z + ((size_t)tile * 128 + rowl) * CD);
                float4 f[16];
#pragma unroll
                for (int i = 0; i < 16; i++) f[i] = zr[i];
                float lb = -3.4e38f; int lj = 0;
#pragma unroll 1
                for (int ii = 0; ii < 8; ii++) {
                    int c = 32 * ii + lane;
                    const float4* er = (const float4*)(smem + SM_B + c * 256);
                    float acc = 0.0f;
#pragma unroll
                    for (int i = 0; i < 16; i++) {
                        float4 e = er[i ^ (c & 15)];
                        acc += f[i].x * e.x + f[i].y * e.y + f[i].z * e.z + f[i].w * e.w;
                    }
                    int j = half * 256 + c;
                    float s = acc - sH[j];
                    if (s > lb) { lb = s; lj = j; }
                }
#pragma unroll
                for (int m = 16; m; m >>= 1) {
                    float ob = __shfl_xor_sync(0xffffffffu, lb, m);
                    int   oj = __shfl_xor_sync(0xffffffffu, lj, m);
                    if (ob > lb || (ob == lb && oj < lj)) { lb = ob; lj = oj; }
                }
                if (lane == 0) {
                    if (half == 0) {
                        sR[li] = make_float4(lb, 0.f, __int_as_float(lj), 0.f);
                    } else {
                        float4 pv = sR[li];
                        int pj = __float_as_int(pv.z);
                        if (pv.x > lb || (pv.x == lb && pj < lj)) { lb = pv.x; lj = pj; }
                        sBI[rowl] = lj;
                    }
                }
            }
            __syncthreads();
        }
    }

    // ---- epilogue: thread t handles row t/4, quarter t%4 ----
    {
        int row = tid >> 2, q = tid & 3;
        int bi = sBI[row];
        size_t rg = (size_t)tile * 128 + row;
        if (q == 0) {
            out[O_IDX + rg] = (float)bi;
            atomicAdd(&sCnt[bi], 1.0f);
        }
        const float4* er = (const float4*)(emb + (size_t)bi * CD + q * 16);
        const float4* zr = (const float4*)(z + rg * CD + q * 16);
        float4* oq = (float4*)(out + O_ZQ + rg * CD + q * 16);
        float* es = g_esum + (size_t)bi * CD + q * 16;
        float lsse = 0.0f;
#pragma unroll
        for (int i = 0; i < 4; i++) {
            float4 e = er[i], zf = zr[i];
            float d0 = e.x - zf.x, d1 = e.y - zf.y, d2 = e.z - zf.z, d3 = e.w - zf.w;
            lsse += d0 * d0 + d1 * d1 + d2 * d2 + d3 * d3;
            oq[i] = make_float4(zf.x + d0, zf.y + d1, zf.z + d2, zf.w + d3);
            asm volatile("red.global.add.v4.f32 [%0], {%1,%2,%3,%4};"
                :: "l"(es + i * 4), "f"(zf.x), "f"(zf.y), "f"(zf.z), "f"(zf.w) : "memory");
        }
#pragma unroll
        for (int m = 16; m; m >>= 1) lsse += __shfl_xor_sync(0xffffffffu, lsse, m);
        if (lane == 0) atomicAdd(&g_sse, lsse);
    }
    __syncthreads();
    {
        float c = sCnt[tid];
        if (c != 0.0f) atomicAdd(&g_counts[tid], c);
    }
}

// ============================================================================
// Kernel 3: finalize EMA + loss
// ============================================================================
__global__ void vq_final(const float* __restrict__ cluster_size,
                         const float* __restrict__ embedding_avg,
                         float* __restrict__ out) {
    __shared__ float red[NC];
    const int j = threadIdx.x;
    float cnt = g_counts[j];
    float ncs = cluster_size[j] * 0.99f + 0.01f * cnt;
    out[O_NCS + j] = ncs;
    red[j] = ncs;
    __syncthreads();
#pragma unroll
    for (int o = NC / 2; o > 0; o >>= 1) {
        if (j < o) red[j] += red[j + o];
        __syncthreads();
    }
    float n  = red[0];
    float cs = (ncs + 1e-6f) / (n + (float)NC * 1e-6f);
#pragma unroll 4
    for (int k = 0; k < CD; k++) {
        float ea = embedding_avg[(size_t)j * CD + k] * 0.99f
                 + 0.01f * g_esum[(size_t)j * CD + k];
        out[O_NAVG + (size_t)j * CD + k] = ea;
        out[O_NEMB + (size_t)j * CD + k] = ea / cs;
    }
    if (j == 0) out[O_LOSS] = 0.25f * g_sse / (float)NELEM;
}

// ============================================================================
extern "C" void kernel_launch(void* const* d_in, const int* in_sizes, int n_in,
                              void* d_out, int out_size) {
    const float* z    = (const float*)d_in[0];
    const float* emb  = (const float*)d_in[1];
    const float* csz  = (const float*)d_in[2];
    const float* eavg = (const float*)d_in[3];
    float* out = (float*)d_out;

    cudaFuncSetAttribute(vq_main, cudaFuncAttributeMaxDynamicSharedMemorySize, SMEM_SZ);
    vq_init<<<64, 512>>>(emb);
    vq_main<<<NROWS / 128, 512, SMEM_SZ>>>(z, emb, out);
    vq_final<<<1, NC>>>(csz, eavg, out);
}